// round 9
// baseline (speedup 1.0000x reference)
#include <cuda_runtime.h>
#include <cuda_fp16.h>
#include <cstdint>

// Problem constants (fixed shapes)
#define NN    50000
#define MMN   12
#define AA    64
#define BB    41
#define FF    169
#define OO    128
#define PAIRS (NN*MMN)     // 600000
#define BN_EPS 1e-5f

// ---------------- scratch (device globals) ----------------
__device__ float   d_PQ[NN * 256];                 // [n][o<128]=P, [n][128+o]=Q
__device__ __half2 d_gh[(long)PAIRS * 64];         // 153.6 MB: g as half2 (ch pairs)
__device__ float   d_ns[NN * AA];
__device__ float   d_s1[OO], d_q1[OO];
__device__ float   d_s2[AA], d_q2[AA];
__device__ float   d_p1s[64][OO], d_p1q[64][OO];   // BN1 partial slots
__device__ float   d_p2s[32][AA], d_p2q[32][AA];   // BN2 partial slots

// ---------------- packed f32x2 helpers ----------------
__device__ __forceinline__ uint64_t pk2(float lo, float hi) {
    uint64_t r; asm("mov.b64 %0, {%1, %2};" : "=l"(r) : "f"(lo), "f"(hi)); return r;
}
__device__ __forceinline__ float2 upk2(uint64_t v) {
    float2 f; asm("mov.b64 {%0, %1}, %2;" : "=f"(f.x), "=f"(f.y) : "l"(v)); return f;
}
__device__ __forceinline__ uint64_t fma2(uint64_t a, uint64_t b, uint64_t c) {
    uint64_t d; asm("fma.rn.f32x2 %0, %1, %2, %3;" : "=l"(d) : "l"(a), "l"(b), "l"(c)); return d;
}
__device__ __forceinline__ uint64_t add2(uint64_t a, uint64_t b) {
    uint64_t d; asm("add.rn.f32x2 %0, %1, %2;" : "=l"(d) : "l"(a), "l"(b)); return d;
}
__device__ __forceinline__ float tanh_ap(float x) {
    float y; asm("tanh.approx.f32 %0, %1;" : "=f"(y) : "f"(x)); return y;
}
__device__ __forceinline__ uint32_t smem_u32(const void* p) {
    uint32_t a;
    asm("{ .reg .u64 t; cvta.to.shared.u64 t, %1; cvt.u32.u64 %0, t; }" : "=r"(a) : "l"(p));
    return a;
}

// ---------------- K0: zero partial-stat slots ----------------
__global__ void kzero() {
    int i = blockIdx.x * blockDim.x + threadIdx.x;
    if (i < 64 * OO) { (&d_p1s[0][0])[i] = 0.f; (&d_p1q[0][0])[i] = 0.f; }
    if (i < 32 * AA) { (&d_p2s[0][0])[i] = 0.f; (&d_p2q[0][0])[i] = 0.f; }
}

// ---------------- K1: PQ = atom @ [W1;W2]^T  (N x 256, K=64) ----------------
__global__ __launch_bounds__(256) void k_pq(const float* __restrict__ atom,
                                            const float* __restrict__ W) {
    __shared__ __align__(16) float As[64 * 64];
    int t  = threadIdx.x;
    int o  = t & 127;
    int f0 = (t >> 7) * 64;

    float w[64];
#pragma unroll
    for (int k = 0; k < 64; k++) w[k] = W[o * FF + f0 + k];

    int row0  = blockIdx.x * 64;
    int nrows = NN - row0; if (nrows > 64) nrows = 64;

    for (int i = t; i < nrows * 64; i += 256) As[i] = atom[row0 * 64 + i];
    __syncthreads();

    for (int r = 0; r < nrows; r++) {
        const float4* ap = (const float4*)&As[r * 64];
        float a0 = 0.f, a1 = 0.f;
#pragma unroll
        for (int k4 = 0; k4 < 16; k4++) {
            float4 v = ap[k4];
            a0 += v.x * w[k4 * 4 + 0] + v.z * w[k4 * 4 + 2];
            a1 += v.y * w[k4 * 4 + 1] + v.w * w[k4 * 4 + 3];
        }
        d_PQ[(row0 + r) * 256 + t] = a0 + a1;
    }
}

// ---------------- K2: main pass (packed FFMA2) ----------------
// Thread owns channel pair (2u, 2u+1); grp = t>>6 handles pairs {2g, 2g+1} of
// each 8-pair batch. x staged DUPLICATED in smem so ld.shared.v2.b64 yields
// packed f32x2 operands with no mov.b64 in the hot loop.
#define PPB2  240
#define GRID2 2500
__global__ __launch_bounds__(256, 2) void k_main(const float* __restrict__ nbr,
                                                 const int*   __restrict__ idx,
                                                 const float* __restrict__ W,
                                                 const float* __restrict__ b) {
    __shared__ __align__(16) float2 nsd[8 * 44];   // duplicated x, k padded to 44
    __shared__ int is[8];
    int t = threadIdx.x;
    int u = t & 63, grp = t >> 6;
    int c0 = 2 * u;

    uint64_t w2[42];
#pragma unroll
    for (int k = 0; k < 42; k++)
        w2[k] = (k < BB) ? pk2(W[c0 * FF + 128 + k], W[(c0 + 1) * FF + 128 + k]) : 0ull;
    uint64_t b2 = pk2(b[c0], b[c0 + 1]);

    // zero pad slots k=41..43 (never rewritten)
    for (int i = t; i < 8 * 3; i += 256) {
        int pp = i / 3, kk = 41 + i % 3;
        nsd[pp * 44 + kk] = make_float2(0.f, 0.f);
    }

    uint32_t nsb = smem_u32(nsd);
    int pbase = blockIdx.x * PPB2;
    uint64_t ls2 = 0ull, lq2 = 0ull;

    for (int gi = 0; gi < PPB2 / 8; gi++) {
        int gb = pbase + gi * 8;
        __syncthreads();
        for (int i = t; i < 8 * BB; i += 256) {
            int pp = i / BB, kk = i - pp * BB;
            float x = nbr[(long)gb * BB + i];
            nsd[pp * 44 + kk] = make_float2(x, x);
        }
        if (t < 8) is[t] = idx[gb + t];
        __syncthreads();

#pragma unroll
        for (int pq = 0; pq < 2; pq++) {
            int pp = grp * 2 + pq;
            int pi = gb + pp;
            int n  = pi / 12;
            int j  = is[pp];
            uint64_t a0 = 0ull, a1 = 0ull;
            uint32_t base = nsb + pp * 352;
#pragma unroll
            for (int k2 = 0; k2 < 21; k2++) {
                uint64_t xa, xb;
                asm volatile("ld.shared.v2.b64 {%0, %1}, [%2];"
                             : "=l"(xa), "=l"(xb) : "r"(base + k2 * 16));
                a0 = fma2(w2[2 * k2],     xa, a0);
                a1 = fma2(w2[2 * k2 + 1], xb, a1);
            }
            uint64_t P2 = *(const uint64_t*)&d_PQ[n * 256 + c0];
            uint64_t Q2 = *(const uint64_t*)&d_PQ[j * 256 + 128 + c0];
            uint64_t gv = add2(add2(a0, a1), add2(add2(P2, Q2), b2));
            float2 g = upk2(gv);
            d_gh[(long)pi * 64 + u] = __floats2half2_rn(g.x, g.y);
            ls2 = add2(ls2, gv);
            lq2 = fma2(gv, gv, lq2);
        }
    }
    float2 s = upk2(ls2), q = upk2(lq2);
    int slot = blockIdx.x & 63;
    atomicAdd(&d_p1s[slot][c0],     s.x);
    atomicAdd(&d_p1s[slot][c0 + 1], s.y);
    atomicAdd(&d_p1q[slot][c0],     q.x);
    atomicAdd(&d_p1q[slot][c0 + 1], q.y);
}

// ---------------- K3: finalize BN1 stats ----------------
__global__ void k_fin1() {
    int t = threadIdx.x;
    if (t < OO) {
        float s = 0.f, q = 0.f;
#pragma unroll
        for (int i = 0; i < 64; i++) { s += d_p1s[i][t]; q += d_p1q[i][t]; }
        d_s1[t] = s; d_q1[t] = q;
    }
}

// ---------------- K4: BN1 + sigmoid*softplus + sum over m + BN2 partials ----
#define GRID4 1480
__global__ __launch_bounds__(256) void k_reduce(const float* __restrict__ g1,
                                                const float* __restrict__ b1) {
    int t = threadIdx.x;
    int u = t & 31, sub = t >> 5;           // 8 n-slots per block
    int a0 = 2 * u;

    float inv = 1.f / (float)PAIRS;
    float mf0 = d_s1[a0] * inv,      mf1 = d_s1[a0 + 1] * inv;
    float vf0 = d_q1[a0] * inv - mf0 * mf0;
    float vf1 = d_q1[a0 + 1] * inv - mf1 * mf1;
    float sf0 = rsqrtf(vf0 + BN_EPS) * g1[a0];
    float sf1 = rsqrtf(vf1 + BN_EPS) * g1[a0 + 1];
    float tf0 = b1[a0] - mf0 * sf0,  tf1 = b1[a0 + 1] - mf1 * sf1;

    float mc0 = d_s1[64 + a0] * inv, mc1 = d_s1[65 + a0] * inv;
    float vc0 = d_q1[64 + a0] * inv - mc0 * mc0;
    float vc1 = d_q1[65 + a0] * inv - mc1 * mc1;
    float sc0 = rsqrtf(vc0 + BN_EPS) * g1[64 + a0];
    float sc1 = rsqrtf(vc1 + BN_EPS) * g1[65 + a0];
    float tc0 = b1[64 + a0] - mc0 * sc0, tc1 = b1[65 + a0] - mc1 * sc1;

    float ls0 = 0.f, ls1 = 0.f, lq0 = 0.f, lq1 = 0.f;
    for (int n = blockIdx.x * 8 + sub; n < NN; n += gridDim.x * 8) {
        const __half2* gp = &d_gh[(long)n * 12 * 64];
        float acc0 = 0.f, acc1 = 0.f;
#pragma unroll
        for (int m = 0; m < 12; m++) {
            float2 xf = __half22float2(gp[m * 64 + u]);
            float2 xc = __half22float2(gp[m * 64 + 32 + u]);
            float f0 = xf.x * sf0 + tf0, f1 = xf.y * sf1 + tf1;
            float c0v = xc.x * sc0 + tc0, c1v = xc.y * sc1 + tc1;
            float sg0 = 0.5f * tanh_ap(0.5f * f0) + 0.5f;
            float sg1 = 0.5f * tanh_ap(0.5f * f1) + 0.5f;
            float sp0 = fmaxf(c0v, 0.f) + __logf(1.f + __expf(-fabsf(c0v)));
            float sp1 = fmaxf(c1v, 0.f) + __logf(1.f + __expf(-fabsf(c1v)));
            acc0 += sg0 * sp0;
            acc1 += sg1 * sp1;
        }
        *(float2*)&d_ns[n * 64 + a0] = make_float2(acc0, acc1);
        ls0 += acc0; lq0 += acc0 * acc0;
        ls1 += acc1; lq1 += acc1 * acc1;
    }
    int slot = blockIdx.x & 31;
    atomicAdd(&d_p2s[slot][a0],     ls0);
    atomicAdd(&d_p2s[slot][a0 + 1], ls1);
    atomicAdd(&d_p2q[slot][a0],     lq0);
    atomicAdd(&d_p2q[slot][a0 + 1], lq1);
}

// ---------------- K5: finalize BN2 stats ----------------
__global__ void k_fin2() {
    int t = threadIdx.x;
    if (t < AA) {
        float s = 0.f, q = 0.f;
#pragma unroll
        for (int i = 0; i < 32; i++) { s += d_p2s[i][t]; q += d_p2q[i][t]; }
        d_s2[t] = s; d_q2[t] = q;
    }
}

// ---------------- K6: BN2 + residual + softplus -> out ----------------------
__global__ __launch_bounds__(256) void k_out(const float* __restrict__ atom,
                                             const float* __restrict__ g2,
                                             const float* __restrict__ b2,
                                             float* __restrict__ out) {
    int i = blockIdx.x * blockDim.x + threadIdx.x;
    if (i >= NN * 64) return;
    int a = i & 63;
    float inv = 1.f / (float)NN;
    float m = d_s2[a] * inv;
    float v = d_q2[a] * inv - m * m;
    float s = rsqrtf(v + BN_EPS) * g2[a];
    float tt = b2[a] - m * s;
    float x = atom[i] + d_ns[i] * s + tt;
    out[i] = fmaxf(x, 0.f) + __logf(1.f + __expf(-fabsf(x)));
}

// ---------------- launch ------------------------------------------------------
extern "C" void kernel_launch(void* const* d_in, const int* in_sizes, int n_in,
                              void* d_out, int out_size) {
    const float* atom = (const float*)d_in[0];   // (N, 64)
    const float* nbr  = (const float*)d_in[1];   // (N, 12, 41)
    const int*   idx  = (const int*)  d_in[2];   // (N, 12)
    const float* W    = (const float*)d_in[3];   // (128, 169)
    const float* b    = (const float*)d_in[4];   // (128,)
    const float* g1   = (const float*)d_in[5];
    const float* b1   = (const float*)d_in[6];
    const float* g2   = (const float*)d_in[7];
    const float* b2   = (const float*)d_in[8];
    float* out = (float*)d_out;

    kzero   <<<16, 512>>>();
    k_pq    <<<(NN + 63) / 64, 256>>>(atom, W);
    k_main  <<<GRID2, 256>>>(nbr, idx, W, b);
    k_fin1  <<<1, 128>>>();
    k_reduce<<<GRID4, 256>>>(g1, b1);
    k_fin2  <<<1, 64>>>();
    k_out   <<<(NN * 64 + 255) / 256, 256>>>(atom, g2, b2, out);
}

// round 10
// speedup vs baseline: 1.0013x; 1.0013x over previous
#include <cuda_runtime.h>
#include <cuda_fp16.h>
#include <cstdint>

// Problem constants (fixed shapes)
#define NN    50000
#define MMN   12
#define AA    64
#define BB    41
#define FF    169
#define OO    128
#define PAIRS (NN*MMN)     // 600000
#define BN_EPS 1e-5f

// ---------------- scratch (device globals) ----------------
__device__ float   d_PQ[NN * 256];                 // [n][o<128]=P, [n][128+o]=Q
__device__ __half2 d_gh[(long)PAIRS * 64];         // 153.6 MB: g as half2 (ch pairs)
__device__ float   d_ns[NN * AA];
__device__ float   d_s1[OO], d_q1[OO];
__device__ float   d_s2[AA], d_q2[AA];
__device__ float   d_p1s[64][OO], d_p1q[64][OO];   // BN1 partial slots
__device__ float   d_p2s[32][AA], d_p2q[32][AA];   // BN2 partial slots

// ---------------- packed f32x2 helpers ----------------
__device__ __forceinline__ uint64_t pk2(float lo, float hi) {
    uint64_t r; asm("mov.b64 %0, {%1, %2};" : "=l"(r) : "f"(lo), "f"(hi)); return r;
}
__device__ __forceinline__ float2 upk2(uint64_t v) {
    float2 f; asm("mov.b64 {%0, %1}, %2;" : "=f"(f.x), "=f"(f.y) : "l"(v)); return f;
}
__device__ __forceinline__ uint64_t fma2(uint64_t a, uint64_t b, uint64_t c) {
    uint64_t d; asm("fma.rn.f32x2 %0, %1, %2, %3;" : "=l"(d) : "l"(a), "l"(b), "l"(c)); return d;
}
__device__ __forceinline__ uint64_t add2(uint64_t a, uint64_t b) {
    uint64_t d; asm("add.rn.f32x2 %0, %1, %2;" : "=l"(d) : "l"(a), "l"(b)); return d;
}
__device__ __forceinline__ float tanh_ap(float x) {
    float y; asm("tanh.approx.f32 %0, %1;" : "=f"(y) : "f"(x)); return y;
}
__device__ __forceinline__ uint32_t smem_u32(const void* p) {
    uint32_t a;
    asm("{ .reg .u64 t; cvta.to.shared.u64 t, %1; cvt.u32.u64 %0, t; }" : "=r"(a) : "l"(p));
    return a;
}

// ---------------- K0: zero partial-stat slots ----------------
__global__ void kzero() {
    int i = blockIdx.x * blockDim.x + threadIdx.x;
    if (i < 64 * OO) { (&d_p1s[0][0])[i] = 0.f; (&d_p1q[0][0])[i] = 0.f; }
    if (i < 32 * AA) { (&d_p2s[0][0])[i] = 0.f; (&d_p2q[0][0])[i] = 0.f; }
}

// ---------------- K1: PQ = atom @ [W1;W2]^T  (N x 256, K=64) ----------------
__global__ __launch_bounds__(256) void k_pq(const float* __restrict__ atom,
                                            const float* __restrict__ W) {
    __shared__ __align__(16) float As[64 * 64];
    int t  = threadIdx.x;
    int o  = t & 127;
    int f0 = (t >> 7) * 64;

    float w[64];
#pragma unroll
    for (int k = 0; k < 64; k++) w[k] = W[o * FF + f0 + k];

    int row0  = blockIdx.x * 64;
    int nrows = NN - row0; if (nrows > 64) nrows = 64;

    for (int i = t; i < nrows * 64; i += 256) As[i] = atom[row0 * 64 + i];
    __syncthreads();

    for (int r = 0; r < nrows; r++) {
        const float4* ap = (const float4*)&As[r * 64];
        float a0 = 0.f, a1 = 0.f;
#pragma unroll
        for (int k4 = 0; k4 < 16; k4++) {
            float4 v = ap[k4];
            a0 += v.x * w[k4 * 4 + 0] + v.z * w[k4 * 4 + 2];
            a1 += v.y * w[k4 * 4 + 1] + v.w * w[k4 * 4 + 3];
        }
        d_PQ[(row0 + r) * 256 + t] = a0 + a1;
    }
}

// ---------------- K2: main pass (packed FFMA2) ----------------
// Thread owns channel pair (2u, 2u+1); grp = t>>6 handles pairs {2g, 2g+1} of
// each 8-pair batch. x staged DUPLICATED in smem so ld.shared.v2.b64 yields
// packed f32x2 operands with no mov.b64 in the hot loop.
#define PPB2  240
#define GRID2 2500
__global__ __launch_bounds__(256, 2) void k_main(const float* __restrict__ nbr,
                                                 const int*   __restrict__ idx,
                                                 const float* __restrict__ W,
                                                 const float* __restrict__ b) {
    __shared__ __align__(16) float2 nsd[8 * 44];   // duplicated x, k padded to 44
    __shared__ int is[8];
    int t = threadIdx.x;
    int u = t & 63, grp = t >> 6;
    int c0 = 2 * u;

    uint64_t w2[42];
#pragma unroll
    for (int k = 0; k < 42; k++)
        w2[k] = (k < BB) ? pk2(W[c0 * FF + 128 + k], W[(c0 + 1) * FF + 128 + k]) : 0ull;
    uint64_t b2 = pk2(b[c0], b[c0 + 1]);

    // zero pad slots k=41..43 (never rewritten)
    for (int i = t; i < 8 * 3; i += 256) {
        int pp = i / 3, kk = 41 + i % 3;
        nsd[pp * 44 + kk] = make_float2(0.f, 0.f);
    }

    uint32_t nsb = smem_u32(nsd);
    int pbase = blockIdx.x * PPB2;
    uint64_t ls2 = 0ull, lq2 = 0ull;

    for (int gi = 0; gi < PPB2 / 8; gi++) {
        int gb = pbase + gi * 8;
        __syncthreads();
        for (int i = t; i < 8 * BB; i += 256) {
            int pp = i / BB, kk = i - pp * BB;
            float x = nbr[(long)gb * BB + i];
            nsd[pp * 44 + kk] = make_float2(x, x);
        }
        if (t < 8) is[t] = idx[gb + t];
        __syncthreads();

#pragma unroll
        for (int pq = 0; pq < 2; pq++) {
            int pp = grp * 2 + pq;
            int pi = gb + pp;
            int n  = pi / 12;
            int j  = is[pp];
            uint64_t a0 = 0ull, a1 = 0ull;
            uint32_t base = nsb + pp * 352;
#pragma unroll
            for (int k2 = 0; k2 < 21; k2++) {
                uint64_t xa, xb;
                asm volatile("ld.shared.v2.b64 {%0, %1}, [%2];"
                             : "=l"(xa), "=l"(xb) : "r"(base + k2 * 16));
                a0 = fma2(w2[2 * k2],     xa, a0);
                a1 = fma2(w2[2 * k2 + 1], xb, a1);
            }
            uint64_t P2 = *(const uint64_t*)&d_PQ[n * 256 + c0];
            uint64_t Q2 = *(const uint64_t*)&d_PQ[j * 256 + 128 + c0];
            uint64_t gv = add2(add2(a0, a1), add2(add2(P2, Q2), b2));
            float2 g = upk2(gv);
            d_gh[(long)pi * 64 + u] = __floats2half2_rn(g.x, g.y);
            ls2 = add2(ls2, gv);
            lq2 = fma2(gv, gv, lq2);
        }
    }
    float2 s = upk2(ls2), q = upk2(lq2);
    int slot = blockIdx.x & 63;
    atomicAdd(&d_p1s[slot][c0],     s.x);
    atomicAdd(&d_p1s[slot][c0 + 1], s.y);
    atomicAdd(&d_p1q[slot][c0],     q.x);
    atomicAdd(&d_p1q[slot][c0 + 1], q.y);
}

// ---------------- K3: finalize BN1 stats ----------------
__global__ void k_fin1() {
    int t = threadIdx.x;
    if (t < OO) {
        float s = 0.f, q = 0.f;
#pragma unroll
        for (int i = 0; i < 64; i++) { s += d_p1s[i][t]; q += d_p1q[i][t]; }
        d_s1[t] = s; d_q1[t] = q;
    }
}

// ---------------- K4: BN1 + sigmoid*softplus + sum over m + BN2 partials ----
#define GRID4 1480
__global__ __launch_bounds__(256) void k_reduce(const float* __restrict__ g1,
                                                const float* __restrict__ b1) {
    int t = threadIdx.x;
    int u = t & 31, sub = t >> 5;           // 8 n-slots per block
    int a0 = 2 * u;

    float inv = 1.f / (float)PAIRS;
    float mf0 = d_s1[a0] * inv,      mf1 = d_s1[a0 + 1] * inv;
    float vf0 = d_q1[a0] * inv - mf0 * mf0;
    float vf1 = d_q1[a0 + 1] * inv - mf1 * mf1;
    float sf0 = rsqrtf(vf0 + BN_EPS) * g1[a0];
    float sf1 = rsqrtf(vf1 + BN_EPS) * g1[a0 + 1];
    float tf0 = b1[a0] - mf0 * sf0,  tf1 = b1[a0 + 1] - mf1 * sf1;

    float mc0 = d_s1[64 + a0] * inv, mc1 = d_s1[65 + a0] * inv;
    float vc0 = d_q1[64 + a0] * inv - mc0 * mc0;
    float vc1 = d_q1[65 + a0] * inv - mc1 * mc1;
    float sc0 = rsqrtf(vc0 + BN_EPS) * g1[64 + a0];
    float sc1 = rsqrtf(vc1 + BN_EPS) * g1[65 + a0];
    float tc0 = b1[64 + a0] - mc0 * sc0, tc1 = b1[65 + a0] - mc1 * sc1;

    float ls0 = 0.f, ls1 = 0.f, lq0 = 0.f, lq1 = 0.f;
    for (int n = blockIdx.x * 8 + sub; n < NN; n += gridDim.x * 8) {
        const __half2* gp = &d_gh[(long)n * 12 * 64];
        float acc0 = 0.f, acc1 = 0.f;
#pragma unroll
        for (int m = 0; m < 12; m++) {
            float2 xf = __half22float2(gp[m * 64 + u]);
            float2 xc = __half22float2(gp[m * 64 + 32 + u]);
            float f0 = xf.x * sf0 + tf0, f1 = xf.y * sf1 + tf1;
            float c0v = xc.x * sc0 + tc0, c1v = xc.y * sc1 + tc1;
            float sg0 = 0.5f * tanh_ap(0.5f * f0) + 0.5f;
            float sg1 = 0.5f * tanh_ap(0.5f * f1) + 0.5f;
            float sp0 = fmaxf(c0v, 0.f) + __logf(1.f + __expf(-fabsf(c0v)));
            float sp1 = fmaxf(c1v, 0.f) + __logf(1.f + __expf(-fabsf(c1v)));
            acc0 += sg0 * sp0;
            acc1 += sg1 * sp1;
        }
        *(float2*)&d_ns[n * 64 + a0] = make_float2(acc0, acc1);
        ls0 += acc0; lq0 += acc0 * acc0;
        ls1 += acc1; lq1 += acc1 * acc1;
    }
    int slot = blockIdx.x & 31;
    atomicAdd(&d_p2s[slot][a0],     ls0);
    atomicAdd(&d_p2s[slot][a0 + 1], ls1);
    atomicAdd(&d_p2q[slot][a0],     lq0);
    atomicAdd(&d_p2q[slot][a0 + 1], lq1);
}

// ---------------- K5: finalize BN2 stats ----------------
__global__ void k_fin2() {
    int t = threadIdx.x;
    if (t < AA) {
        float s = 0.f, q = 0.f;
#pragma unroll
        for (int i = 0; i < 32; i++) { s += d_p2s[i][t]; q += d_p2q[i][t]; }
        d_s2[t] = s; d_q2[t] = q;
    }
}

// ---------------- K6: BN2 + residual + softplus -> out ----------------------
__global__ __launch_bounds__(256) void k_out(const float* __restrict__ atom,
                                             const float* __restrict__ g2,
                                             const float* __restrict__ b2,
                                             float* __restrict__ out) {
    int i = blockIdx.x * blockDim.x + threadIdx.x;
    if (i >= NN * 64) return;
    int a = i & 63;
    float inv = 1.f / (float)NN;
    float m = d_s2[a] * inv;
    float v = d_q2[a] * inv - m * m;
    float s = rsqrtf(v + BN_EPS) * g2[a];
    float tt = b2[a] - m * s;
    float x = atom[i] + d_ns[i] * s + tt;
    out[i] = fmaxf(x, 0.f) + __logf(1.f + __expf(-fabsf(x)));
}

// ---------------- launch ------------------------------------------------------
extern "C" void kernel_launch(void* const* d_in, const int* in_sizes, int n_in,
                              void* d_out, int out_size) {
    const float* atom = (const float*)d_in[0];   // (N, 64)
    const float* nbr  = (const float*)d_in[1];   // (N, 12, 41)
    const int*   idx  = (const int*)  d_in[2];   // (N, 12)
    const float* W    = (const float*)d_in[3];   // (128, 169)
    const float* b    = (const float*)d_in[4];   // (128,)
    const float* g1   = (const float*)d_in[5];
    const float* b1   = (const float*)d_in[6];
    const float* g2   = (const float*)d_in[7];
    const float* b2   = (const float*)d_in[8];
    float* out = (float*)d_out;

    kzero   <<<16, 512>>>();
    k_pq    <<<(NN + 63) / 64, 256>>>(atom, W);
    k_main  <<<GRID2, 256>>>(nbr, idx, W, b);
    k_fin1  <<<1, 128>>>();
    k_reduce<<<GRID4, 256>>>(g1, b1);
    k_fin2  <<<1, 64>>>();
    k_out   <<<(NN * 64 + 255) / 256, 256>>>(atom, g2, b2, out);
}